// round 17
// baseline (speedup 1.0000x reference)
#include <cuda_runtime.h>
#include <cuda_fp16.h>
#include <cstdint>

// Problem constants
#define BATCH 8
#define SEQ   2048
#define EMB   1024
#define HD    64
#define MROWS (BATCH*SEQ)      // 16384
#define SCALE 0.03125f         // 1024^-0.5
#define LOG2E 1.4426950408889634f

// Scratch (device globals: no allocation allowed)
// q: fp16 pre-scaled by SCALE*log2e; k, v: fp16
__device__ __half g_q[MROWS*HD];
__device__ __half g_k[MROWS*HD];
__device__ __half g_v[MROWS*HD];

// ---------------------------------------------------------------------------
// helpers
// ---------------------------------------------------------------------------
__device__ __forceinline__ uint32_t pkh(float hi_val, float lo_val) {
    uint32_t d;
    asm("cvt.rn.f16x2.f32 %0, %1, %2;" : "=r"(d) : "f"(hi_val), "f"(lo_val));
    return d;
}
// packed 2^x on fp16 pairs
__device__ __forceinline__ uint32_t ex2h2(uint32_t v) {
    uint32_t d;
    asm("ex2.approx.f16x2 %0, %1;" : "=r"(d) : "r"(v));
    return d;
}
__device__ __forceinline__ uint32_t smem_u32(const void* p) {
    uint32_t a;
    asm("{ .reg .u64 t; cvta.to.shared.u64 t, %1; cvt.u32.u64 %0, t; }"
        : "=r"(a) : "l"(p));
    return a;
}
__device__ __forceinline__ void ldsm4(uint32_t* r, uint32_t addr) {
    asm volatile("ldmatrix.sync.aligned.m8n8.x4.shared.b16 {%0,%1,%2,%3}, [%4];"
        : "=r"(r[0]), "=r"(r[1]), "=r"(r[2]), "=r"(r[3]) : "r"(addr));
}
__device__ __forceinline__ void ldsm4t(uint32_t* r, uint32_t addr) {
    asm volatile("ldmatrix.sync.aligned.m8n8.x4.trans.shared.b16 {%0,%1,%2,%3}, [%4];"
        : "=r"(r[0]), "=r"(r[1]), "=r"(r[2]), "=r"(r[3]) : "r"(addr));
}
__device__ __forceinline__ void mma16816(float* d, const uint32_t* a,
                                         uint32_t b0, uint32_t b1) {
    asm("mma.sync.aligned.m16n8k16.row.col.f32.f16.f16.f32 "
        "{%0,%1,%2,%3}, {%4,%5,%6,%7}, {%8,%9}, {%0,%1,%2,%3};"
        : "+f"(d[0]), "+f"(d[1]), "+f"(d[2]), "+f"(d[3])
        : "r"(a[0]), "r"(a[1]), "r"(a[2]), "r"(a[3]), "r"(b0), "r"(b1));
}

// ---------------------------------------------------------------------------
// Kernel 1: QKV projection via mma.sync fp16 single product, with IN-KERNEL
// weight conversion (fp32 W loaded per chunk, converted during staging).
// W smem tile: [64 k-rows][192 n] fp16, row stride 200 halfs (400 B -> each
// ldsm row-set covers all 32 banks; conflict-free). B-fragments via
// ldmatrix.trans (same pattern as attn's V path).
// grid = 128, block = 256 (2x4 warp grid, 64Mx48N each). BK=64, double-buffered.
// ---------------------------------------------------------------------------
#define QSTR 144                   // X smem row stride bytes (72 fp16)
#define WSTR 200                   // W smem row stride in halfs
#define XH_OFF 0
#define WH_OFF 9216                // 128*72 halfs
#define QBUF_ELEMS (9216 + 64*WSTR)            // 22016
#define QKV_SMEM_BYTES (2 * QBUF_ELEMS * 2)    // 88064

__global__ __launch_bounds__(256) void qkv_tc_kernel(
    const float* __restrict__ x,
    const float* __restrict__ Wq,
    const float* __restrict__ Wk,
    const float* __restrict__ Wv)
{
    extern __shared__ __half qs[];
    const uint32_t uBase = smem_u32(qs);

    const int tid  = threadIdx.x;
    const int wid  = tid >> 5;
    const int lane = tid & 31;
    const int wm   = wid >> 2;
    const int wn   = wid & 3;
    const int m4   = lane >> 3;
    const int r8   = lane & 7;
    const int g    = lane >> 2;
    const int tg   = lane & 3;
    const int row0 = blockIdx.x * 128;

    const int xr  = tid >> 1;
    const int xc0 = (tid & 1) * 32;

    float acc[4][6][4] = {};
    float4 xv[8];
    float2 wv[24];

#define LOADX(c) do { \
    _Pragma("unroll") \
    for (int j = 0; j < 8; j++) \
        xv[j] = *(const float4*)&x[(size_t)(row0 + xr) * EMB + (c) * 64 + xc0 + j * 4]; \
    _Pragma("unroll") \
    for (int j = 0; j < 24; j++) { \
        int gi = tid + j * 256; \
        int k = gi / 96, p = gi % 96; \
        int mat = p >> 5, n = (p & 31) * 2; \
        const float* Wm = (mat == 0) ? Wq : (mat == 1) ? Wk : Wv; \
        wv[j] = *(const float2*)&Wm[(size_t)((c) * 64 + k) * 64 + n]; \
    } \
} while (0)

#define STOREB(b) do { \
    __half* base = qs + (b) * QBUF_ELEMS; \
    _Pragma("unroll") \
    for (int j = 0; j < 8; j++) { \
        uint32_t h0 = pkh(xv[j].y, xv[j].x); \
        uint32_t h1 = pkh(xv[j].w, xv[j].z); \
        *(uint2*)(base + XH_OFF + xr * 72 + xc0 + j * 4) = make_uint2(h0, h1); \
    } \
    _Pragma("unroll") \
    for (int j = 0; j < 24; j++) { \
        int gi = tid + j * 256; \
        int k = gi / 96, p = gi % 96; \
        *(uint32_t*)(base + WH_OFF + k * WSTR + p * 2) = pkh(wv[j].y, wv[j].x); \
    } \
} while (0)

    LOADX(0);
    STOREB(0);

    for (int c = 0; c < 16; c++) {
        const int cur = c & 1;
        if (c < 15) LOADX(c + 1);
        __syncthreads();
        if (c < 15) STOREB(cur ^ 1);

        const uint32_t uB  = uBase + cur * (QBUF_ELEMS * 2);
        const uint32_t uXh = uB + XH_OFF * 2;
        const uint32_t uWh = uB + WH_OFF * 2;

#pragma unroll
        for (int kcb = 0; kcb < 4; kcb += 2) {
            uint32_t ah[4][2][4];
#pragma unroll
            for (int mf = 0; mf < 4; mf++)
#pragma unroll
                for (int kk = 0; kk < 2; kk++) {
                    uint32_t off = (uint32_t)((wm * 64 + mf * 16 + (m4 & 1) * 8 + r8) * QSTR
                                   + ((kcb + kk) * 16 + (m4 >> 1) * 8) * 2);
                    ldsm4(ah[mf][kk], uXh + off);
                }
#pragma unroll
            for (int nf = 0; nf < 6; nf++) {
                uint32_t bh[4];
                uint32_t off = (uint32_t)((kcb * 16 + (m4 & 1) * 8 + (m4 >> 1) * 16 + r8)
                               * (WSTR * 2) + (wn * 48 + nf * 8) * 2);
                ldsm4t(bh, uWh + off);
#pragma unroll
                for (int mf = 0; mf < 4; mf++) {
                    mma16816(acc[mf][nf], ah[mf][0], bh[0], bh[1]);
                    mma16816(acc[mf][nf], ah[mf][1], bh[2], bh[3]);
                }
            }
        }
    }

    // epilogue: q -> fp16 (scaled by SCALE*log2e for ex2 softmax); k,v -> fp16
#pragma unroll
    for (int mf = 0; mf < 4; mf++) {
        const int r0 = row0 + wm * 64 + mf * 16 + g;
#pragma unroll
        for (int nf = 0; nf < 6; nf++) {
            const int n   = wn * 48 + nf * 8 + 2 * tg;
            const int mat = n >> 6;
            const int lc  = n & 63;
            float v0 = acc[mf][nf][0], v1 = acc[mf][nf][1];
            float v2 = acc[mf][nf][2], v3 = acc[mf][nf][3];
            __half* oh;
            if (mat == 0) {
                const float qs_ = SCALE * LOG2E;
                v0 *= qs_; v1 *= qs_; v2 *= qs_; v3 *= qs_;
                oh = g_q;
            } else {
                oh = (mat == 1) ? g_k : g_v;
            }
            *(uint32_t*)&oh[(size_t)r0 * 64 + lc]       = pkh(v1, v0);
            *(uint32_t*)&oh[(size_t)(r0 + 8) * 64 + lc] = pkh(v3, v2);
        }
    }
#undef LOADX
#undef STOREB
}

// ---------------------------------------------------------------------------
// Kernel 2: causal flash attention, fp16 single-product, pipelined K/V,
// no-max softmax via ex2.approx.f16x2 (q pre-scaled by log2e), row-sums l
// accumulated by a ones-column MMA. 128 threads. grid = 128 (batch x 16
// pairs); each CTA does q-tiles (31-pair) then (pair) => 33 uniform steps.
// ---------------------------------------------------------------------------
#define SROW 72                       // smem row stride in fp16 elems
// half-elem offsets: K0 V0 K1 V1 Q, each 64*SROW = 4608 halfs
#define AK(b) ((b) * 9216)
#define AV(b) ((b) * 9216 + 4608)
#define AQ    18432
#define ATTN_SMEM_BYTES ((18432 + 4608) * 2)   // 46080

__global__ __launch_bounds__(128) void attn_kernel(float* __restrict__ out)
{
    extern __shared__ __half smh[];
    const uint32_t uBase = smem_u32(smh);
    const uint32_t uQ    = uBase + AQ * 2;

    const int bid   = blockIdx.x;
    const int batch = bid & 7;
    const int pair  = bid >> 3;         // 0..15

    const int tid  = threadIdx.x;
    const int wq   = tid >> 5;          // warp 0..3, q rows wq*16..+15
    const int lane = tid & 31;
    const int g    = lane >> 2;
    const int tg   = lane & 3;
    const int m4   = lane >> 3;
    const int r8   = lane & 7;

    const uint32_t ONES = 0x3C003C00u;  // fp16 {1, 1}

    const size_t bb = (size_t)batch * SEQ * HD;
    const __half* gq = g_q + bb;
    const __half* gk = g_k + bb;
    const __half* gv = g_v + bb;
    float* ob = out + bb;

    // staging mapping: thread -> (row, 32-elem half-row)
    const int srow = tid >> 1;
    const int scol = (tid & 1) * 32;

    for (int t = 0; t < 2; t++) {
        const int qt = t ? pair : (31 - pair);
        const int q0 = qt * 64;

        __syncthreads();   // previous tile's reads fully done
        // stage Q (full 32-half span per thread) + prologue K/V(kt=0) loads
        uint4 pf[8];
        {
            const uint4* sq = (const uint4*)(gq + (size_t)(q0 + srow) * HD + scol);
            uint4 t0 = sq[0], t1 = sq[1], t2 = sq[2], t3 = sq[3];
            const uint4* s0 = (const uint4*)(gk + (size_t)srow * HD + scol);
            const uint4* s1 = (const uint4*)(gv + (size_t)srow * HD + scol);
#pragma unroll
            for (int j = 0; j < 4; j++) { pf[j] = s0[j]; pf[4 + j] = s1[j]; }
            *(uint4*)(smh + AQ + srow * SROW + scol)      = t0;
            *(uint4*)(smh + AQ + srow * SROW + scol + 8)  = t1;
            *(uint4*)(smh + AQ + srow * SROW + scol + 16) = t2;
            *(uint4*)(smh + AQ + srow * SROW + scol + 24) = t3;
        }
        __syncthreads();

        uint32_t qh[4][4];
        {
            const int qrow = wq * 16 + ((m4 & 1) << 3) + r8;
#pragma unroll
            for (int kc = 0; kc < 4; kc++) {
                uint32_t off = (uint32_t)(qrow * (SROW * 2) + (kc * 16 + (m4 >> 1) * 8) * 2);
                ldsm4(qh[kc], uQ + off);
            }
        }

        float o[8][4] = {};
        float lacc[4] = {};               // ones-column MMA accumulator: row sums
        const int qrow0 = q0 + wq * 16 + g;
        const int qrow1 = qrow0 + 8;

        for (int kt = 0; kt <= qt; kt++) {
            const int cur = kt & 1;
            const uint32_t uK = uBase + AK(cur) * 2;
            const uint32_t uV = uBase + AV(cur) * 2;

            // ---- publish this step's K/V (loaded last iteration) ----
#pragma unroll
            for (int j = 0; j < 4; j++) {
                *(uint4*)(smh + AK(cur) + srow * SROW + scol + 8 * j) = pf[j];
                *(uint4*)(smh + AV(cur) + srow * SROW + scol + 8 * j) = pf[4 + j];
            }
            // ---- issue next step's gmem loads (latency hides under compute) ----
            if (kt < qt) {
                const int k1 = (kt + 1) * 64;
                const uint4* s0 = (const uint4*)(gk + (size_t)(k1 + srow) * HD + scol);
                const uint4* s1 = (const uint4*)(gv + (size_t)(k1 + srow) * HD + scol);
#pragma unroll
                for (int j = 0; j < 4; j++) { pf[j] = s0[j]; pf[4 + j] = s1[j]; }
            }
            __syncthreads();   // buf[cur] visible; reads of buf[cur] from step
                               // kt-2 ordered before this STS by sync(kt-1)

            // ---- S' = (log2e * S) via pre-scaled q ----
            float sf[8][4];
#pragma unroll
            for (int nf = 0; nf < 8; nf++) {
                sf[nf][0] = sf[nf][1] = sf[nf][2] = sf[nf][3] = 0.f;
#pragma unroll
                for (int kcb = 0; kcb < 4; kcb += 2) {
                    uint32_t bh[4];
                    uint32_t off = (uint32_t)((nf * 8 + r8) * (SROW * 2) +
                                   (kcb * 16 + (m4 & 1) * 8 + (m4 >> 1) * 16) * 2);
                    ldsm4(bh, uK + off);
                    mma16816(sf[nf], qh[kcb],     bh[0], bh[1]);
                    mma16816(sf[nf], qh[kcb + 1], bh[2], bh[3]);
                }
            }

            // ---- causal mask (diagonal tile) ----
            if (kt == qt) {
                const int k0 = kt * 64;
#pragma unroll
                for (int nf = 0; nf < 8; nf++) {
                    const int col = k0 + nf * 8 + 2 * tg;
                    if (col     > qrow0) sf[nf][0] = -1e30f;
                    if (col + 1 > qrow0) sf[nf][1] = -1e30f;
                    if (col     > qrow1) sf[nf][2] = -1e30f;
                    if (col + 1 > qrow1) sf[nf][3] = -1e30f;
                }
            }

            // ---- P = 2^(S') : cvt to f16x2 then packed ex2 ----
            uint32_t ph[4][4];
#pragma unroll
            for (int kc = 0; kc < 4; kc++) {
                const int f0 = 2 * kc, f1 = 2 * kc + 1;
                ph[kc][0] = ex2h2(pkh(sf[f0][1], sf[f0][0]));
                ph[kc][1] = ex2h2(pkh(sf[f0][3], sf[f0][2]));
                ph[kc][2] = ex2h2(pkh(sf[f1][1], sf[f1][0]));
                ph[kc][3] = ex2h2(pkh(sf[f1][3], sf[f1][2]));
            }

            // ---- l += P * ones (exact fp32 tensor accumulation) ----
#pragma unroll
            for (int kc = 0; kc < 4; kc++)
                mma16816(lacc, ph[kc], ONES, ONES);

            // ---- O += P V ----
#pragma unroll
            for (int nf = 0; nf < 8; nf++) {
#pragma unroll
                for (int kcb = 0; kcb < 4; kcb += 2) {
                    uint32_t bh[4];
                    uint32_t off = (uint32_t)((kcb * 16 + (m4 & 1) * 8 + (m4 >> 1) * 16 + r8)
                                   * (SROW * 2) + nf * 16);
                    ldsm4t(bh, uV + off);
                    mma16816(o[nf], ph[kcb],     bh[0], bh[1]);
                    mma16816(o[nf], ph[kcb + 1], bh[2], bh[3]);
                }
            }
        }

        // ---- epilogue: l is in the MMA accumulator (all cols = row sum) ----
        const float inv0 = 1.f / lacc[0];
        const float inv1 = 1.f / lacc[2];
#pragma unroll
        for (int nf = 0; nf < 8; nf++) {
            *(float2*)&ob[(size_t)qrow0 * HD + nf * 8 + 2 * tg] =
                make_float2(o[nf][0] * inv0, o[nf][1] * inv0);
            *(float2*)&ob[(size_t)qrow1 * HD + nf * 8 + 2 * tg] =
                make_float2(o[nf][2] * inv1, o[nf][3] * inv1);
        }
    }
}

// ---------------------------------------------------------------------------
extern "C" void kernel_launch(void* const* d_in, const int* in_sizes, int n_in,
                              void* d_out, int out_size)
{
    const float* x  = (const float*)d_in[0];
    const float* Wq = (const float*)d_in[1];
    const float* Wk = (const float*)d_in[2];
    const float* Wv = (const float*)d_in[3];
    float* out = (float*)d_out;

    static bool attr_set = false;
    if (!attr_set) {
        cudaFuncSetAttribute(attn_kernel,
                             cudaFuncAttributeMaxDynamicSharedMemorySize,
                             ATTN_SMEM_BYTES);
        cudaFuncSetAttribute(qkv_tc_kernel,
                             cudaFuncAttributeMaxDynamicSharedMemorySize,
                             QKV_SMEM_BYTES);
        attr_set = true;
    }

    qkv_tc_kernel<<<MROWS / 128, 256, QKV_SMEM_BYTES>>>(x, Wq, Wk, Wv);
    attn_kernel<<<BATCH * 16, 128, ATTN_SMEM_BYTES>>>(out);
}